// round 1
// baseline (speedup 1.0000x reference)
#include <cuda_runtime.h>

#define NN 50000
#define EE 400000
#define TT 4
#define DIN 64
#define DD 128
#define BG 64
#define NSTEPS 8

// ---------------- device scratch (no allocations allowed) ----------------
__device__ float g_h [NN * DD];          // current hidden state
__device__ float g_h1[NN * DD];          // padded input (residual)
__device__ float g_t [NN * TT * DD];     // per-type transformed nodes [N,T,D]
__device__ float g_a [NN * DD];          // aggregated messages
__device__ float g_gi[NN * 3 * DD];      // a @ w_ih + b_ih
__device__ float g_gh[NN * 3 * DD];      // h @ w_hh + b_hh
__device__ float g_feats[BG * DD];       // per-graph pooled features

// ---------------- init: h1 = [features | 0], h = h1 ----------------
__global__ void init_kernel(const float* __restrict__ features) {
    int idx = blockIdx.x * blockDim.x + threadIdx.x;
    if (idx >= NN * DD) return;
    int n = idx >> 7, j = idx & 127;
    float v = (j < DIN) ? features[n * DIN + j] : 0.f;
    g_h1[idx] = v;
    g_h [idx] = v;
}

// ---------------- transform: t[n, tt, :] = h[n,:] @ W_msg[tt] + b_msg[tt]
// tile: 64 rows x 128 cols, 256 threads, thread tile 4x8, K-chunks of 32
__global__ __launch_bounds__(256) void transform_kernel(
        const float* __restrict__ Wmsg, const float* __restrict__ bmsg) {
    const int tt   = blockIdx.y;
    const int row0 = blockIdx.x * 64;
    __shared__ float As[32][68];   // [k][row], 68 keeps 16B alignment
    __shared__ float Bs[32][128];  // [k][col]
    const int tid = threadIdx.x;
    const int tx  = tid & 15;      // col group (8 cols)
    const int ty  = tid >> 4;      // row group (4 rows)

    float acc[4][8];
#pragma unroll
    for (int i = 0; i < 4; i++)
#pragma unroll
        for (int j = 0; j < 8; j++) acc[i][j] = 0.f;

    const float* Wt = Wmsg + tt * DD * DD;

    for (int k0 = 0; k0 < DD; k0 += 32) {
        // A: 64 rows x 32 k = 512 float4 -> 2 per thread, store transposed
#pragma unroll
        for (int i = 0; i < 2; i++) {
            int f = tid + 256 * i;
            int r = f >> 3, kq = f & 7;
            int grow = row0 + r;
            float4 v = make_float4(0.f, 0.f, 0.f, 0.f);
            if (grow < NN) v = *(const float4*)&g_h[grow * DD + k0 + kq * 4];
            As[kq * 4 + 0][r] = v.x;
            As[kq * 4 + 1][r] = v.y;
            As[kq * 4 + 2][r] = v.z;
            As[kq * 4 + 3][r] = v.w;
        }
        // B: 32 x 128 = 1024 float4 -> 4 per thread
#pragma unroll
        for (int i = 0; i < 4; i++) {
            int f = tid + 256 * i;
            int kr = f >> 5, cq = f & 31;
            *(float4*)&Bs[kr][cq * 4] =
                *(const float4*)&Wt[(k0 + kr) * DD + cq * 4];
        }
        __syncthreads();
#pragma unroll
        for (int k = 0; k < 32; k++) {
            float4 av = *(const float4*)&As[k][ty * 4];
            float4 b0 = *(const float4*)&Bs[k][tx * 8];
            float4 b1 = *(const float4*)&Bs[k][tx * 8 + 4];
            float a_[4] = {av.x, av.y, av.z, av.w};
            float b_[8] = {b0.x, b0.y, b0.z, b0.w, b1.x, b1.y, b1.z, b1.w};
#pragma unroll
            for (int i = 0; i < 4; i++)
#pragma unroll
                for (int j = 0; j < 8; j++) acc[i][j] += a_[i] * b_[j];
        }
        __syncthreads();
    }
#pragma unroll
    for (int i = 0; i < 4; i++) {
        int grow = row0 + ty * 4 + i;
        if (grow >= NN) continue;
#pragma unroll
        for (int j = 0; j < 8; j++) {
            int c = tx * 8 + j;
            g_t[(size_t)grow * (TT * DD) + tt * DD + c] =
                acc[i][j] + bmsg[tt * DD + c];
        }
    }
}

// ---------------- zero a ----------------
__global__ void zero_a_kernel() {
    int idx = blockIdx.x * blockDim.x + threadIdx.x;
    if (idx < NN * DD / 4)
        ((float4*)g_a)[idx] = make_float4(0.f, 0.f, 0.f, 0.f);
}

// ---------------- scatter: a[dst] += t[src, etype]  (warp per edge) -----
__global__ __launch_bounds__(256) void scatter_kernel(
        const int* __restrict__ src, const int* __restrict__ dst,
        const int* __restrict__ et) {
    int e = blockIdx.x * 8 + (threadIdx.x >> 5);
    if (e >= EE) return;
    int lane = threadIdx.x & 31;
    int s = src[e], d = dst[e], t = et[e];
    float4 v = *(const float4*)&g_t[(size_t)s * (TT * DD) + t * DD + lane * 4];
    float* ap = &g_a[d * DD + lane * 4];
    atomicAdd(ap + 0, v.x);
    atomicAdd(ap + 1, v.y);
    atomicAdd(ap + 2, v.z);
    atomicAdd(ap + 3, v.w);
}

// ---------------- gates GEMM: gi = a@w_ih + b_ih, gh = h@w_hh + b_hh ----
// tile: 32 rows x 128 cols (of 384), both matrices in one block.
__global__ __launch_bounds__(256) void gates_kernel(
        const float* __restrict__ wih, const float* __restrict__ bih,
        const float* __restrict__ whh, const float* __restrict__ bhh) {
    const int cb   = blockIdx.y;        // column block 0..2
    const int row0 = blockIdx.x * 32;
    __shared__ float Aa[32][36];
    __shared__ float Ah[32][36];
    __shared__ float Bi[32][128];
    __shared__ float Bh[32][128];
    const int tid = threadIdx.x;
    const int tx  = tid & 15;           // 8 cols
    const int ty  = tid >> 4;           // 2 rows

    float ai[2][8], ah[2][8];
#pragma unroll
    for (int i = 0; i < 2; i++)
#pragma unroll
        for (int j = 0; j < 8; j++) { ai[i][j] = 0.f; ah[i][j] = 0.f; }

    for (int k0 = 0; k0 < DD; k0 += 32) {
        {
            int r = tid >> 3, kq = tid & 7;
            int grow = row0 + r;
            float4 va = make_float4(0.f, 0.f, 0.f, 0.f), vh = va;
            if (grow < NN) {
                va = *(const float4*)&g_a[grow * DD + k0 + kq * 4];
                vh = *(const float4*)&g_h[grow * DD + k0 + kq * 4];
            }
            Aa[kq * 4 + 0][r] = va.x; Aa[kq * 4 + 1][r] = va.y;
            Aa[kq * 4 + 2][r] = va.z; Aa[kq * 4 + 3][r] = va.w;
            Ah[kq * 4 + 0][r] = vh.x; Ah[kq * 4 + 1][r] = vh.y;
            Ah[kq * 4 + 2][r] = vh.z; Ah[kq * 4 + 3][r] = vh.w;
        }
#pragma unroll
        for (int i = 0; i < 4; i++) {
            int f = tid + 256 * i;
            int kr = f >> 5, cq = f & 31;
            *(float4*)&Bi[kr][cq * 4] =
                *(const float4*)&wih[(k0 + kr) * 384 + cb * 128 + cq * 4];
            *(float4*)&Bh[kr][cq * 4] =
                *(const float4*)&whh[(k0 + kr) * 384 + cb * 128 + cq * 4];
        }
        __syncthreads();
#pragma unroll
        for (int k = 0; k < 32; k++) {
            float2 aav = *(const float2*)&Aa[k][ty * 2];
            float2 ahv = *(const float2*)&Ah[k][ty * 2];
            float4 i0 = *(const float4*)&Bi[k][tx * 8];
            float4 i1 = *(const float4*)&Bi[k][tx * 8 + 4];
            float4 h0 = *(const float4*)&Bh[k][tx * 8];
            float4 h1 = *(const float4*)&Bh[k][tx * 8 + 4];
            float bi_[8] = {i0.x, i0.y, i0.z, i0.w, i1.x, i1.y, i1.z, i1.w};
            float bh_[8] = {h0.x, h0.y, h0.z, h0.w, h1.x, h1.y, h1.z, h1.w};
#pragma unroll
            for (int j = 0; j < 8; j++) {
                ai[0][j] += aav.x * bi_[j];
                ai[1][j] += aav.y * bi_[j];
                ah[0][j] += ahv.x * bh_[j];
                ah[1][j] += ahv.y * bh_[j];
            }
        }
        __syncthreads();
    }
#pragma unroll
    for (int i = 0; i < 2; i++) {
        int grow = row0 + ty * 2 + i;
        if (grow >= NN) continue;
#pragma unroll
        for (int j = 0; j < 8; j++) {
            int c = cb * 128 + tx * 8 + j;
            g_gi[(size_t)grow * 384 + c] = ai[i][j] + bih[c];
            g_gh[(size_t)grow * 384 + c] = ah[i][j] + bhh[c];
        }
    }
}

// ---------------- GRU pointwise update ----------------
__global__ void gru_kernel() {
    int idx = blockIdx.x * blockDim.x + threadIdx.x;
    if (idx >= NN * DD) return;
    int n = idx >> 7, j = idx & 127;
    const float* gi = g_gi + (size_t)n * 384;
    const float* gh = g_gh + (size_t)n * 384;
    float ir = gi[j], iz = gi[128 + j], inn = gi[256 + j];
    float hr = gh[j], hz = gh[128 + j], hn  = gh[256 + j];
    float r  = 1.f / (1.f + expf(-(ir + hr)));
    float z  = 1.f / (1.f + expf(-(iz + hz)));
    float ng = tanhf(inn + r * hn);
    float h  = g_h[idx];
    g_h[idx] = (1.f - z) * ng + z * h;
}

// ---------------- pooling ----------------
__global__ void zero_feats_kernel() {
    int i = blockIdx.x * blockDim.x + threadIdx.x;
    if (i < BG * DD) g_feats[i] = 0.f;
}

// block = 128 threads (one per feature), each block handles 64 sorted nodes
__global__ void pool_kernel(const int* __restrict__ n2g) {
    int n0 = blockIdx.x * 64;
    int j  = threadIdx.x;
    if (n0 >= NN) return;
    float acc = 0.f;
    int cur = n2g[n0];
    for (int i = 0; i < 64; i++) {
        int n = n0 + i;
        if (n >= NN) break;
        int g = n2g[n];
        if (g != cur) {
            atomicAdd(&g_feats[cur * DD + j], acc);
            acc = 0.f; cur = g;
        }
        acc += g_h[n * DD + j] + g_h1[n * DD + j];
    }
    atomicAdd(&g_feats[cur * DD + j], acc);
}

// ---------------- classifier ----------------
__global__ void cls_kernel(const float* __restrict__ Wc,
                           const float* __restrict__ bc,
                           float* __restrict__ out) {
    int tid = threadIdx.x;
    if (tid >= BG * 2) return;
    int g = tid >> 1, c = tid & 1;
    float s = bc[c];
#pragma unroll 8
    for (int k = 0; k < DD; k++) s += g_feats[g * DD + k] * Wc[k * 2 + c];
    out[g * 2 + c] = s;
}

// ---------------- launch ----------------
extern "C" void kernel_launch(void* const* d_in, const int* in_sizes, int n_in,
                              void* d_out, int out_size) {
    const float* features = (const float*)d_in[0];
    const int*   src      = (const int*)  d_in[1];
    const int*   dst      = (const int*)  d_in[2];
    const int*   etype    = (const int*)  d_in[3];
    const int*   n2g      = (const int*)  d_in[4];
    const float* W_msg    = (const float*)d_in[5];
    const float* b_msg    = (const float*)d_in[6];
    const float* w_ih     = (const float*)d_in[7];
    const float* b_ih     = (const float*)d_in[8];
    const float* w_hh     = (const float*)d_in[9];
    const float* b_hh     = (const float*)d_in[10];
    const float* W_cls    = (const float*)d_in[11];
    const float* b_cls    = (const float*)d_in[12];
    float* out = (float*)d_out;

    init_kernel<<<(NN * DD + 255) / 256, 256>>>(features);

    for (int s = 0; s < NSTEPS; s++) {
        transform_kernel<<<dim3((NN + 63) / 64, TT), 256>>>(W_msg, b_msg);
        zero_a_kernel<<<(NN * DD / 4 + 255) / 256, 256>>>();
        scatter_kernel<<<(EE + 7) / 8, 256>>>(src, dst, etype);
        gates_kernel<<<dim3((NN + 31) / 32, 3), 256>>>(w_ih, b_ih, w_hh, b_hh);
        gru_kernel<<<(NN * DD + 255) / 256, 256>>>();
    }

    zero_feats_kernel<<<(BG * DD + 255) / 256, 256>>>();
    pool_kernel<<<(NN + 63) / 64, 128>>>(n2g);
    cls_kernel<<<1, 128>>>(W_cls, b_cls, out);
}

// round 3
// speedup vs baseline: 3.0743x; 3.0743x over previous
#include <cuda_runtime.h>
#include <cuda_bf16.h>
#include <cstdint>

#define NN 50000
#define EE 400000
#define TT 4
#define DIN 64
#define DD 128
#define BG 64
#define NSTEPS 8
#define RTILES ((NN + 127) / 128)   // 391

// ---------------- device scratch ----------------
__device__ float g_h [NN * DD];
__device__ float g_h1[NN * DD];
__device__ float g_t [NN * TT * DD];     // [N][512]
__device__ float g_a [NN * DD];
__device__ float g_gi[NN * 3 * DD];
__device__ float g_gh[NN * 3 * DD];
__device__ float g_feats[BG * DD];
// prepped bf16 hi/lo weights, B layout [col][k] (k contiguous)
__device__ __nv_bfloat16 g_Wt_hi [TT * DD * DD];
__device__ __nv_bfloat16 g_Wt_lo [TT * DD * DD];
__device__ __nv_bfloat16 g_Bih_hi[3 * DD * DD];
__device__ __nv_bfloat16 g_Bih_lo[3 * DD * DD];
__device__ __nv_bfloat16 g_Bhh_hi[3 * DD * DD];
__device__ __nv_bfloat16 g_Bhh_lo[3 * DD * DD];

// ---------------- mma helpers (base-ISA, compiles for compute_103) -------
__device__ __forceinline__ uint32_t smem_u32(const void* p) {
    return (uint32_t)__cvta_generic_to_shared(p);
}
__device__ __forceinline__ void ldsm_x4(uint32_t* r, uint32_t addr) {
    asm volatile("ldmatrix.sync.aligned.m8n8.x4.shared.b16 {%0,%1,%2,%3}, [%4];"
                 : "=r"(r[0]), "=r"(r[1]), "=r"(r[2]), "=r"(r[3]) : "r"(addr));
}
__device__ __forceinline__ void mma16816(float* d, const uint32_t* a, const uint32_t* b) {
    asm volatile(
        "mma.sync.aligned.m16n8k16.row.col.f32.bf16.bf16.f32 "
        "{%0,%1,%2,%3}, {%4,%5,%6,%7}, {%8,%9}, {%0,%1,%2,%3};"
        : "+f"(d[0]), "+f"(d[1]), "+f"(d[2]), "+f"(d[3])
        : "r"(a[0]), "r"(a[1]), "r"(a[2]), "r"(a[3]), "r"(b[0]), "r"(b[1]));
}

// padded bf16 tile: 128 rows x 136 cols (272B row stride -> conflict-free ldmatrix)
#define TROW 136
#define TILE_B (128 * TROW * 2)   // 34816

// ---------------- generic 3-term split GEMM ----------------
// C[row0+0..127][colbase+0..127] = A[128 rows x128] @ B_chunk^T + bias
// A fp32 row-major [nrows][128]; B prepped bf16 [cols][128]; chunk = blockIdx.y
__global__ __launch_bounds__(256, 1) void gemm3_kernel(
        const float* __restrict__ A, int nrows,
        const __nv_bfloat16* __restrict__ Bhi, const __nv_bfloat16* __restrict__ Blo,
        const float* __restrict__ bias, float* __restrict__ C, int ldc) {
    extern __shared__ char smem[];
    char* sAH = smem;
    char* sAL = smem + TILE_B;
    char* sBH = smem + 2 * TILE_B;
    char* sBL = smem + 3 * TILE_B;
    const int tid  = threadIdx.x;
    const int wid  = tid >> 5, lane = tid & 31;
    const int wm   = wid & 3, wn = wid >> 2;       // warp tile 32x64 in 4x2 grid
    const int row0 = blockIdx.x * 128;
    const int colbase = blockIdx.y * 128;
    const __nv_bfloat16* Bh = Bhi + blockIdx.y * (DD * DD);
    const __nv_bfloat16* Bl = Blo + blockIdx.y * (DD * DD);

    // ---- load A (fp32 -> hi/lo bf16 split) ----
#pragma unroll
    for (int i = 0; i < 16; i++) {
        int f = tid + 256 * i;                 // 4096 float4 chunks
        int r = f >> 5, c4 = (f & 31) * 4;
        int gr = row0 + r;
        float4 v = make_float4(0.f, 0.f, 0.f, 0.f);
        if (gr < nrows) v = *(const float4*)(A + (size_t)gr * DD + c4);
        __nv_bfloat16 h0 = __float2bfloat16(v.x), h1 = __float2bfloat16(v.y);
        __nv_bfloat16 h2 = __float2bfloat16(v.z), h3 = __float2bfloat16(v.w);
        __nv_bfloat16 l0 = __float2bfloat16(v.x - __bfloat162float(h0));
        __nv_bfloat16 l1 = __float2bfloat16(v.y - __bfloat162float(h1));
        __nv_bfloat16 l2 = __float2bfloat16(v.z - __bfloat162float(h2));
        __nv_bfloat16 l3 = __float2bfloat16(v.w - __bfloat162float(h3));
        __nv_bfloat162 hp0 = {h0, h1}, hp1 = {h2, h3};
        __nv_bfloat162 lp0 = {l0, l1}, lp1 = {l2, l3};
        uint32_t off = r * (TROW * 2) + c4 * 2;
        *(uint2*)(sAH + off) = make_uint2(*(uint32_t*)&hp0, *(uint32_t*)&hp1);
        *(uint2*)(sAL + off) = make_uint2(*(uint32_t*)&lp0, *(uint32_t*)&lp1);
    }
    // ---- load B (already bf16) ----
#pragma unroll
    for (int i = 0; i < 8; i++) {
        int f = tid + 256 * i;                 // 2048 uint4 chunks of 8 bf16
        int r = f >> 4, c8 = (f & 15) * 8;
        uint32_t off = r * (TROW * 2) + c8 * 2;
        *(uint4*)(sBH + off) = *(const uint4*)(Bh + r * DD + c8);
        *(uint4*)(sBL + off) = *(const uint4*)(Bl + r * DD + c8);
    }
    __syncthreads();

    // per-lane ldmatrix base offsets
    const uint32_t aoff = (uint32_t)((wm * 32 + (lane & 15)) * (TROW * 2) + (lane >> 4) * 16);
    const uint32_t boff = (uint32_t)((wn * 64 + ((lane >> 4) & 1) * 8 + (lane & 7)) * (TROW * 2)
                                     + ((lane >> 3) & 1) * 16);
    const uint32_t uAH = smem_u32(sAH), uAL = smem_u32(sAL);
    const uint32_t uBH = smem_u32(sBH), uBL = smem_u32(sBL);

    float acc[2][8][4];
#pragma unroll
    for (int mi = 0; mi < 2; mi++)
#pragma unroll
        for (int n8 = 0; n8 < 8; n8++)
#pragma unroll
            for (int j = 0; j < 4; j++) acc[mi][n8][j] = 0.f;

#pragma unroll
    for (int t = 0; t < 3; t++) {
        uint32_t ua = (t < 2) ? uAH : uAL;
        uint32_t ub = (t == 1) ? uBL : uBH;
#pragma unroll
        for (int k = 0; k < 8; k++) {
            uint32_t kb = k * 32;
            uint32_t afr[2][4], bfr[4][4];
            ldsm_x4(afr[0], ua + aoff + kb);
            ldsm_x4(afr[1], ua + aoff + kb + 16 * (TROW * 2));
#pragma unroll
            for (int ni = 0; ni < 4; ni++)
                ldsm_x4(bfr[ni], ub + boff + kb + ni * 16 * (TROW * 2));
#pragma unroll
            for (int mi = 0; mi < 2; mi++)
#pragma unroll
                for (int ni = 0; ni < 4; ni++) {
                    mma16816(acc[mi][ni * 2 + 0], afr[mi], &bfr[ni][0]);
                    mma16816(acc[mi][ni * 2 + 1], afr[mi], &bfr[ni][2]);
                }
        }
    }

    // ---- epilogue: bias + store (float2 per frag half) ----
#pragma unroll
    for (int mi = 0; mi < 2; mi++) {
        int r0 = row0 + wm * 32 + mi * 16 + (lane >> 2);
#pragma unroll
        for (int n8 = 0; n8 < 8; n8++) {
            int col = colbase + wn * 64 + n8 * 8 + (lane & 3) * 2;
            float b0 = bias[col], b1 = bias[col + 1];
            if (r0 < nrows)
                *(float2*)(C + (size_t)r0 * ldc + col) =
                    make_float2(acc[mi][n8][0] + b0, acc[mi][n8][1] + b1);
            if (r0 + 8 < nrows)
                *(float2*)(C + (size_t)(r0 + 8) * ldc + col) =
                    make_float2(acc[mi][n8][2] + b0, acc[mi][n8][3] + b1);
        }
    }
}

// ---------------- weight prep ----------------
__global__ void prep_wmsg(const float* __restrict__ Wmsg) {
    int idx = blockIdx.x * blockDim.x + threadIdx.x;
    if (idx >= TT * DD * DD) return;
    int t = idx >> 14, rem = idx & 16383, e = rem >> 7, d = rem & 127;
    float w = Wmsg[t * 16384 + d * 128 + e];            // W[t][d][e] -> B[t][e][d]
    __nv_bfloat16 hi = __float2bfloat16(w);
    g_Wt_hi[idx] = hi;
    g_Wt_lo[idx] = __float2bfloat16(w - __bfloat162float(hi));
}
__global__ void prep_gates(const float* __restrict__ wih, const float* __restrict__ whh) {
    int idx = blockIdx.x * blockDim.x + threadIdx.x;
    if (idx >= 3 * DD * DD) return;
    int c = idx >> 7, k = idx & 127;
    float wi = wih[k * 384 + c];
    float wh = whh[k * 384 + c];
    __nv_bfloat16 hi = __float2bfloat16(wi);
    g_Bih_hi[idx] = hi;
    g_Bih_lo[idx] = __float2bfloat16(wi - __bfloat162float(hi));
    __nv_bfloat16 hh = __float2bfloat16(wh);
    g_Bhh_hi[idx] = hh;
    g_Bhh_lo[idx] = __float2bfloat16(wh - __bfloat162float(hh));
}

// ---------------- init ----------------
__global__ void init_kernel(const float* __restrict__ features) {
    int idx = blockIdx.x * blockDim.x + threadIdx.x;
    if (idx >= NN * DD) return;
    int n = idx >> 7, j = idx & 127;
    float v = (j < DIN) ? features[n * DIN + j] : 0.f;
    g_h1[idx] = v;
    g_h [idx] = v;
}

// ---------------- zero a ----------------
__global__ void zero_a_kernel() {
    int idx = blockIdx.x * blockDim.x + threadIdx.x;
    if (idx < NN * DD / 4)
        ((float4*)g_a)[idx] = make_float4(0.f, 0.f, 0.f, 0.f);
}

// ---------------- scatter ----------------
__global__ __launch_bounds__(256) void scatter_kernel(
        const int* __restrict__ src, const int* __restrict__ dst,
        const int* __restrict__ et) {
    int e = blockIdx.x * 8 + (threadIdx.x >> 5);
    if (e >= EE) return;
    int lane = threadIdx.x & 31;
    int s = src[e], d = dst[e], t = et[e];
    float4 v = *(const float4*)&g_t[(size_t)s * (TT * DD) + t * DD + lane * 4];
    float* ap = &g_a[d * DD + lane * 4];
    atomicAdd(ap + 0, v.x);
    atomicAdd(ap + 1, v.y);
    atomicAdd(ap + 2, v.z);
    atomicAdd(ap + 3, v.w);
}

// ---------------- GRU pointwise ----------------
__global__ void gru_kernel() {
    int idx = blockIdx.x * blockDim.x + threadIdx.x;
    if (idx >= NN * DD) return;
    int n = idx >> 7, j = idx & 127;
    const float* gi = g_gi + (size_t)n * 384;
    const float* gh = g_gh + (size_t)n * 384;
    float ir = gi[j], iz = gi[128 + j], inn = gi[256 + j];
    float hr = gh[j], hz = gh[128 + j], hn  = gh[256 + j];
    float r  = 1.f / (1.f + expf(-(ir + hr)));
    float z  = 1.f / (1.f + expf(-(iz + hz)));
    float ng = tanhf(inn + r * hn);
    float h  = g_h[idx];
    g_h[idx] = (1.f - z) * ng + z * h;
}

// ---------------- pooling + classifier ----------------
__global__ void zero_feats_kernel() {
    int i = blockIdx.x * blockDim.x + threadIdx.x;
    if (i < BG * DD) g_feats[i] = 0.f;
}
__global__ void pool_kernel(const int* __restrict__ n2g) {
    int n0 = blockIdx.x * 64;
    int j  = threadIdx.x;
    if (n0 >= NN) return;
    float acc = 0.f;
    int cur = n2g[n0];
    for (int i = 0; i < 64; i++) {
        int n = n0 + i;
        if (n >= NN) break;
        int g = n2g[n];
        if (g != cur) {
            atomicAdd(&g_feats[cur * DD + j], acc);
            acc = 0.f; cur = g;
        }
        acc += g_h[n * DD + j] + g_h1[n * DD + j];
    }
    atomicAdd(&g_feats[cur * DD + j], acc);
}
__global__ void cls_kernel(const float* __restrict__ Wc,
                           const float* __restrict__ bc,
                           float* __restrict__ out) {
    int tid = threadIdx.x;
    if (tid >= BG * 2) return;
    int g = tid >> 1, c = tid & 1;
    float s = bc[c];
#pragma unroll 8
    for (int k = 0; k < DD; k++) s += g_feats[g * DD + k] * Wc[k * 2 + c];
    out[g * 2 + c] = s;
}

// ---------------- launch ----------------
#define GSMEM (4 * TILE_B)   // 139264

extern "C" void kernel_launch(void* const* d_in, const int* in_sizes, int n_in,
                              void* d_out, int out_size) {
    const float* features = (const float*)d_in[0];
    const int*   src      = (const int*)  d_in[1];
    const int*   dst      = (const int*)  d_in[2];
    const int*   etype    = (const int*)  d_in[3];
    const int*   n2g      = (const int*)  d_in[4];
    const float* W_msg    = (const float*)d_in[5];
    const float* b_msg    = (const float*)d_in[6];
    const float* w_ih     = (const float*)d_in[7];
    const float* b_ih     = (const float*)d_in[8];
    const float* w_hh     = (const float*)d_in[9];
    const float* b_hh     = (const float*)d_in[10];
    const float* W_cls    = (const float*)d_in[11];
    const float* b_cls    = (const float*)d_in[12];
    float* out = (float*)d_out;

    static int smem_set = 0;
    if (!smem_set) {
        cudaFuncSetAttribute(gemm3_kernel,
                             cudaFuncAttributeMaxDynamicSharedMemorySize, GSMEM);
        smem_set = 1;
    }

    // device-global pointers usable as kernel args
    float *p_h, *p_a, *p_gi, *p_gh, *p_t;
    __nv_bfloat16 *p_Wh, *p_Wl, *p_ih_h, *p_ih_l, *p_hh_h, *p_hh_l;
    cudaGetSymbolAddress((void**)&p_h,  g_h);
    cudaGetSymbolAddress((void**)&p_a,  g_a);
    cudaGetSymbolAddress((void**)&p_gi, g_gi);
    cudaGetSymbolAddress((void**)&p_gh, g_gh);
    cudaGetSymbolAddress((void**)&p_t,  g_t);
    cudaGetSymbolAddress((void**)&p_Wh, g_Wt_hi);
    cudaGetSymbolAddress((void**)&p_Wl, g_Wt_lo);
    cudaGetSymbolAddress((void**)&p_ih_h, g_Bih_hi);
    cudaGetSymbolAddress((void**)&p_ih_l, g_Bih_lo);
    cudaGetSymbolAddress((void**)&p_hh_h, g_Bhh_hi);
    cudaGetSymbolAddress((void**)&p_hh_l, g_Bhh_lo);

    prep_wmsg<<<(TT * DD * DD + 255) / 256, 256>>>(W_msg);
    prep_gates<<<(3 * DD * DD + 255) / 256, 256>>>(w_ih, w_hh);
    init_kernel<<<(NN * DD + 255) / 256, 256>>>(features);

    for (int s = 0; s < NSTEPS; s++) {
        gemm3_kernel<<<dim3(RTILES, TT), 256, GSMEM>>>(
            p_h, NN, p_Wh, p_Wl, b_msg, p_t, TT * DD);
        zero_a_kernel<<<(NN * DD / 4 + 255) / 256, 256>>>();
        scatter_kernel<<<(EE + 7) / 8, 256>>>(src, dst, etype);
        gemm3_kernel<<<dim3(RTILES, 3), 256, GSMEM>>>(
            p_a, NN, p_ih_h, p_ih_l, b_ih, p_gi, 3 * DD);
        gemm3_kernel<<<dim3(RTILES, 3), 256, GSMEM>>>(
            p_h, NN, p_hh_h, p_hh_l, b_hh, p_gh, 3 * DD);
        gru_kernel<<<(NN * DD + 255) / 256, 256>>>();
    }

    zero_feats_kernel<<<(BG * DD + 255) / 256, 256>>>();
    pool_kernel<<<(NN + 63) / 64, 128>>>(n2g);
    cls_kernel<<<1, 128>>>(W_cls, b_cls, out);
}

// round 4
// speedup vs baseline: 4.3539x; 1.4162x over previous
#include <cuda_runtime.h>
#include <cuda_bf16.h>
#include <cstdint>

#define NN 50000
#define EE 400000
#define TT 4
#define DIN 64
#define DD 128
#define BG 64
#define NSTEPS 8
#define RTILES ((NN + 127) / 128)   // 391
#define NB1 ((NN + 255) / 256)      // 196 scan blocks

// ---------------- device scratch ----------------
__device__ float g_h [NN * DD];
__device__ float g_h1[NN * DD];
__device__ float g_t [NN * TT * DD];     // [N][512]
__device__ float g_a [NN * DD];
__device__ float g_rs[NN * DD];          // r gate sum (a@wih_r + h@whh_r)
__device__ float g_zs[NN * DD];          // z gate sum
__device__ float g_in[NN * DD];          // i_n = a@wih_n
__device__ float g_hn[NN * DD];          // h_n = h@whh_n
__device__ float g_feats[BG * DD];
// CSR by dst
__device__ int g_cnt [NN];
__device__ int g_scan[NN];
__device__ int g_off [NN + 1];
__device__ int g_part [256];
__device__ int g_part2[256];
__device__ int g_eoff[EE];               // per-edge rank within dst bucket
__device__ int g_gsrc[EE];               // CSR payload: src*512 + etype*128
// prepped bf16 hi/lo weights, B layout [col][k]
__device__ __nv_bfloat16 g_Wt_hi [TT * DD * DD];
__device__ __nv_bfloat16 g_Wt_lo [TT * DD * DD];
__device__ __nv_bfloat16 g_Bih_hi[3 * DD * DD];
__device__ __nv_bfloat16 g_Bih_lo[3 * DD * DD];
__device__ __nv_bfloat16 g_Bhh_hi[3 * DD * DD];
__device__ __nv_bfloat16 g_Bhh_lo[3 * DD * DD];

// ---------------- mma helpers ----------------
__device__ __forceinline__ uint32_t smem_u32(const void* p) {
    return (uint32_t)__cvta_generic_to_shared(p);
}
__device__ __forceinline__ void ldsm_x4(uint32_t* r, uint32_t addr) {
    asm volatile("ldmatrix.sync.aligned.m8n8.x4.shared.b16 {%0,%1,%2,%3}, [%4];"
                 : "=r"(r[0]), "=r"(r[1]), "=r"(r[2]), "=r"(r[3]) : "r"(addr));
}
__device__ __forceinline__ void mma16816(float* d, const uint32_t* a, const uint32_t* b) {
    asm volatile(
        "mma.sync.aligned.m16n8k16.row.col.f32.bf16.bf16.f32 "
        "{%0,%1,%2,%3}, {%4,%5,%6,%7}, {%8,%9}, {%0,%1,%2,%3};"
        : "+f"(d[0]), "+f"(d[1]), "+f"(d[2]), "+f"(d[3])
        : "r"(a[0]), "r"(a[1]), "r"(a[2]), "r"(a[3]), "r"(b[0]), "r"(b[1]));
}

#define TROW 136
#define TILE_B (128 * TROW * 2)   // 34816

// fp32 -> hi/lo bf16 split into padded smem tile
__device__ __forceinline__ void load_f32_split_tile(char* hi, char* lo,
        const float* __restrict__ src, int row0, int nrows, int tid) {
#pragma unroll
    for (int i = 0; i < 16; i++) {
        int f = tid + 256 * i;
        int r = f >> 5, c4 = (f & 31) * 4;
        int gr = row0 + r;
        float4 v = make_float4(0.f, 0.f, 0.f, 0.f);
        if (gr < nrows) v = *(const float4*)(src + (size_t)gr * DD + c4);
        __nv_bfloat16 h0 = __float2bfloat16(v.x), h1 = __float2bfloat16(v.y);
        __nv_bfloat16 h2 = __float2bfloat16(v.z), h3 = __float2bfloat16(v.w);
        __nv_bfloat16 l0 = __float2bfloat16(v.x - __bfloat162float(h0));
        __nv_bfloat16 l1 = __float2bfloat16(v.y - __bfloat162float(h1));
        __nv_bfloat16 l2 = __float2bfloat16(v.z - __bfloat162float(h2));
        __nv_bfloat16 l3 = __float2bfloat16(v.w - __bfloat162float(h3));
        __nv_bfloat162 hp0 = {h0, h1}, hp1 = {h2, h3};
        __nv_bfloat162 lp0 = {l0, l1}, lp1 = {l2, l3};
        uint32_t off = r * (TROW * 2) + c4 * 2;
        *(uint2*)(hi + off) = make_uint2(*(uint32_t*)&hp0, *(uint32_t*)&hp1);
        *(uint2*)(lo + off) = make_uint2(*(uint32_t*)&lp0, *(uint32_t*)&lp1);
    }
}
__device__ __forceinline__ void load_b_tile(char* bh, char* bl,
        const __nv_bfloat16* __restrict__ Bh, const __nv_bfloat16* __restrict__ Bl, int tid) {
#pragma unroll
    for (int i = 0; i < 8; i++) {
        int f = tid + 256 * i;
        int r = f >> 4, c8 = (f & 15) * 8;
        uint32_t off = r * (TROW * 2) + c8 * 2;
        *(uint4*)(bh + off) = *(const uint4*)(Bh + r * DD + c8);
        *(uint4*)(bl + off) = *(const uint4*)(Bl + r * DD + c8);
    }
}

// 3-term split K=128 accumulate into acc[2][8][4]
__device__ __forceinline__ void mma_accum_3term(float acc[2][8][4],
        uint32_t uAH, uint32_t uAL, uint32_t uBH, uint32_t uBL,
        uint32_t aoff, uint32_t boff) {
#pragma unroll
    for (int t = 0; t < 3; t++) {
        uint32_t ua = (t < 2) ? uAH : uAL;
        uint32_t ub = (t == 1) ? uBL : uBH;
#pragma unroll
        for (int k = 0; k < 8; k++) {
            uint32_t kb = k * 32;
            uint32_t afr[2][4], bfr[4][4];
            ldsm_x4(afr[0], ua + aoff + kb);
            ldsm_x4(afr[1], ua + aoff + kb + 16 * (TROW * 2));
#pragma unroll
            for (int ni = 0; ni < 4; ni++)
                ldsm_x4(bfr[ni], ub + boff + kb + ni * 16 * (TROW * 2));
#pragma unroll
            for (int mi = 0; mi < 2; mi++)
#pragma unroll
                for (int ni = 0; ni < 4; ni++) {
                    mma16816(acc[mi][ni * 2 + 0], afr[mi], &bfr[ni][0]);
                    mma16816(acc[mi][ni * 2 + 1], afr[mi], &bfr[ni][2]);
                }
        }
    }
}

// ---------------- transform GEMM: g_t = h @ Wmsg[y]^T + bmsg ----------------
__global__ __launch_bounds__(256, 1) void gemm3_kernel(
        const float* __restrict__ A, int nrows,
        const __nv_bfloat16* __restrict__ Bhi, const __nv_bfloat16* __restrict__ Blo,
        const float* __restrict__ bias, float* __restrict__ C, int ldc) {
    extern __shared__ char smem[];
    char* sAH = smem;
    char* sAL = smem + TILE_B;
    char* sBH = smem + 2 * TILE_B;
    char* sBL = smem + 3 * TILE_B;
    const int tid  = threadIdx.x;
    const int wid  = tid >> 5, lane = tid & 31;
    const int wm   = wid & 3, wn = wid >> 2;
    const int row0 = blockIdx.x * 128;
    const int colbase = blockIdx.y * 128;

    load_f32_split_tile(sAH, sAL, A, row0, nrows, tid);
    load_b_tile(sBH, sBL, Bhi + blockIdx.y * (DD * DD), Blo + blockIdx.y * (DD * DD), tid);
    __syncthreads();

    const uint32_t aoff = (uint32_t)((wm * 32 + (lane & 15)) * (TROW * 2) + (lane >> 4) * 16);
    const uint32_t boff = (uint32_t)((wn * 64 + ((lane >> 4) & 1) * 8 + (lane & 7)) * (TROW * 2)
                                     + ((lane >> 3) & 1) * 16);
    float acc[2][8][4];
#pragma unroll
    for (int mi = 0; mi < 2; mi++)
#pragma unroll
        for (int n8 = 0; n8 < 8; n8++)
#pragma unroll
            for (int j = 0; j < 4; j++) acc[mi][n8][j] = 0.f;

    mma_accum_3term(acc, smem_u32(sAH), smem_u32(sAL), smem_u32(sBH), smem_u32(sBL),
                    aoff, boff);

#pragma unroll
    for (int mi = 0; mi < 2; mi++) {
        int r0 = row0 + wm * 32 + mi * 16 + (lane >> 2);
#pragma unroll
        for (int n8 = 0; n8 < 8; n8++) {
            int col = colbase + wn * 64 + n8 * 8 + (lane & 3) * 2;
            float b0 = bias[col], b1 = bias[col + 1];
            if (r0 < nrows)
                *(float2*)(C + (size_t)r0 * ldc + col) =
                    make_float2(acc[0 + mi][n8][0] + b0, acc[mi][n8][1] + b1);
            if (r0 + 8 < nrows)
                *(float2*)(C + (size_t)(r0 + 8) * ldc + col) =
                    make_float2(acc[mi][n8][2] + b0, acc[mi][n8][3] + b1);
        }
    }
}

// ---------------- fused gates GEMM ----------------
// y=0: g_rs = a@wih_r + h@whh_r ; y=1: g_zs ; y=2: g_in = a@wih_n ; y=3: g_hn = h@whh_n
#define G6SMEM (6 * TILE_B)   // 208896
__global__ __launch_bounds__(256, 1) void gates_tc() {
    extern __shared__ char smem[];
    char* sAaH = smem;
    char* sAaL = smem + TILE_B;
    char* sAhH = smem + 2 * TILE_B;
    char* sAhL = smem + 3 * TILE_B;
    char* sBH  = smem + 4 * TILE_B;
    char* sBL  = smem + 5 * TILE_B;
    const int tid = threadIdx.x;
    const int wid = tid >> 5, lane = tid & 31;
    const int wm  = wid & 3, wn = wid >> 2;
    const int row0 = blockIdx.x * 128;
    const int y = blockIdx.y;
    const int chunk = (y < 2) ? y : 2;

    if (y != 3) load_f32_split_tile(sAaH, sAaL, g_a, row0, NN, tid);
    if (y != 2) load_f32_split_tile(sAhH, sAhL, g_h, row0, NN, tid);
    // pass-1 B: wih chunk (y=0,1,2) or whh_n (y=3)
    if (y == 3) load_b_tile(sBH, sBL, g_Bhh_hi + 2 * 16384, g_Bhh_lo + 2 * 16384, tid);
    else        load_b_tile(sBH, sBL, g_Bih_hi + chunk * 16384, g_Bih_lo + chunk * 16384, tid);
    __syncthreads();

    const uint32_t aoff = (uint32_t)((wm * 32 + (lane & 15)) * (TROW * 2) + (lane >> 4) * 16);
    const uint32_t boff = (uint32_t)((wn * 64 + ((lane >> 4) & 1) * 8 + (lane & 7)) * (TROW * 2)
                                     + ((lane >> 3) & 1) * 16);
    float acc[2][8][4];
#pragma unroll
    for (int mi = 0; mi < 2; mi++)
#pragma unroll
        for (int n8 = 0; n8 < 8; n8++)
#pragma unroll
            for (int j = 0; j < 4; j++) acc[mi][n8][j] = 0.f;

    // pass 1: A = a (y=0,1,2) or h (y=3)
    {
        uint32_t uH = (y == 3) ? smem_u32(sAhH) : smem_u32(sAaH);
        uint32_t uL = (y == 3) ? smem_u32(sAhL) : smem_u32(sAaL);
        mma_accum_3term(acc, uH, uL, smem_u32(sBH), smem_u32(sBL), aoff, boff);
    }
    // pass 2 (r,z only): A = h, B = whh chunk
    if (y < 2) {
        __syncthreads();
        load_b_tile(sBH, sBL, g_Bhh_hi + chunk * 16384, g_Bhh_lo + chunk * 16384, tid);
        __syncthreads();
        mma_accum_3term(acc, smem_u32(sAhH), smem_u32(sAhL),
                        smem_u32(sBH), smem_u32(sBL), aoff, boff);
    }

    float* C = (y == 0) ? g_rs : (y == 1) ? g_zs : (y == 2) ? g_in : g_hn;
#pragma unroll
    for (int mi = 0; mi < 2; mi++) {
        int r0 = row0 + wm * 32 + mi * 16 + (lane >> 2);
#pragma unroll
        for (int n8 = 0; n8 < 8; n8++) {
            int col = wn * 64 + n8 * 8 + (lane & 3) * 2;
            if (r0 < NN)
                *(float2*)(C + (size_t)r0 * DD + col) =
                    make_float2(acc[mi][n8][0], acc[mi][n8][1]);
            if (r0 + 8 < NN)
                *(float2*)(C + (size_t)(r0 + 8) * DD + col) =
                    make_float2(acc[mi][n8][2], acc[mi][n8][3]);
        }
    }
}

// ---------------- weight prep ----------------
__global__ void prep_wmsg(const float* __restrict__ Wmsg) {
    int idx = blockIdx.x * blockDim.x + threadIdx.x;
    if (idx >= TT * DD * DD) return;
    int t = idx >> 14, rem = idx & 16383, e = rem >> 7, d = rem & 127;
    float w = Wmsg[t * 16384 + d * 128 + e];
    __nv_bfloat16 hi = __float2bfloat16(w);
    g_Wt_hi[idx] = hi;
    g_Wt_lo[idx] = __float2bfloat16(w - __bfloat162float(hi));
}
__global__ void prep_gates(const float* __restrict__ wih, const float* __restrict__ whh) {
    int idx = blockIdx.x * blockDim.x + threadIdx.x;
    if (idx >= 3 * DD * DD) return;
    int c = idx >> 7, k = idx & 127;
    float wi = wih[k * 384 + c];
    float wh = whh[k * 384 + c];
    __nv_bfloat16 hi = __float2bfloat16(wi);
    g_Bih_hi[idx] = hi;
    g_Bih_lo[idx] = __float2bfloat16(wi - __bfloat162float(hi));
    __nv_bfloat16 hh = __float2bfloat16(wh);
    g_Bhh_hi[idx] = hh;
    g_Bhh_lo[idx] = __float2bfloat16(wh - __bfloat162float(hh));
}

// ---------------- init ----------------
__global__ void init_kernel(const float* __restrict__ features) {
    int idx = blockIdx.x * blockDim.x + threadIdx.x;
    if (idx >= NN * DD) return;
    int n = idx >> 7, j = idx & 127;
    float v = (j < DIN) ? features[n * DIN + j] : 0.f;
    g_h1[idx] = v;
    g_h [idx] = v;
}

// ---------------- CSR build ----------------
__global__ void zero_cnt_kernel() {
    int i = blockIdx.x * blockDim.x + threadIdx.x;
    if (i < NN) g_cnt[i] = 0;
}
__global__ void count_kernel(const int* __restrict__ dst) {
    int e = blockIdx.x * blockDim.x + threadIdx.x;
    if (e >= EE) return;
    g_eoff[e] = atomicAdd(&g_cnt[dst[e]], 1);
}
__global__ void scan_a_kernel() {
    __shared__ int s[256];
    int b = blockIdx.x, t = threadIdx.x;
    int n = b * 256 + t;
    int v = (n < NN) ? g_cnt[n] : 0;
    s[t] = v;
    __syncthreads();
    for (int d = 1; d < 256; d <<= 1) {
        int x = (t >= d) ? s[t - d] : 0;
        __syncthreads();
        s[t] += x;
        __syncthreads();
    }
    if (n < NN) g_scan[n] = s[t] - v;
    if (t == 255) g_part[b] = s[255];
}
__global__ void scan_b_kernel() {
    __shared__ int s[256];
    int t = threadIdx.x;
    int v = (t < NB1) ? g_part[t] : 0;
    s[t] = v;
    __syncthreads();
    for (int d = 1; d < 256; d <<= 1) {
        int x = (t >= d) ? s[t - d] : 0;
        __syncthreads();
        s[t] += x;
        __syncthreads();
    }
    g_part2[t] = s[t] - v;
}
__global__ void scan_c_kernel() {
    int n = blockIdx.x * blockDim.x + threadIdx.x;
    if (n < NN) g_off[n] = g_scan[n] + g_part2[n >> 8];
    if (n == 0) g_off[NN] = EE;
}
__global__ void fill_kernel(const int* __restrict__ src, const int* __restrict__ dst,
                            const int* __restrict__ et) {
    int e = blockIdx.x * blockDim.x + threadIdx.x;
    if (e >= EE) return;
    int pos = g_off[dst[e]] + g_eoff[e];
    g_gsrc[pos] = src[e] * 512 + et[e] * 128;
}

// ---------------- gather: a[d] = sum of t[src,etype] over in-edges -------
__global__ __launch_bounds__(256) void gather_kernel() {
    int w = blockIdx.x * 8 + (threadIdx.x >> 5);
    if (w >= NN) return;
    int lane = threadIdx.x & 31;
    int b0 = g_off[w], b1 = g_off[w + 1];
    float4 acc = make_float4(0.f, 0.f, 0.f, 0.f);
    for (int i = b0; i < b1; i++) {
        int so = g_gsrc[i];
        float4 v = *(const float4*)&g_t[so + lane * 4];
        acc.x += v.x; acc.y += v.y; acc.z += v.z; acc.w += v.w;
    }
    *(float4*)&g_a[w * DD + lane * 4] = acc;
}

// ---------------- GRU pointwise ----------------
__global__ void gru_kernel(const float* __restrict__ bih, const float* __restrict__ bhh) {
    int idx = blockIdx.x * blockDim.x + threadIdx.x;
    if (idx >= NN * 32) return;
    int n = idx >> 5, q = idx & 31;
    int col = q * 4;
    size_t o = (size_t)n * DD + col;
    float4 rs = *(const float4*)&g_rs[o];
    float4 zs = *(const float4*)&g_zs[o];
    float4 iv = *(const float4*)&g_in[o];
    float4 hv = *(const float4*)&g_hn[o];
    float4 h  = *(const float4*)&g_h [o];
    float4 br  = *(const float4*)&bih[col];
    float4 br2 = *(const float4*)&bhh[col];
    float4 bz  = *(const float4*)&bih[128 + col];
    float4 bz2 = *(const float4*)&bhh[128 + col];
    float4 bn  = *(const float4*)&bih[256 + col];
    float4 bn2 = *(const float4*)&bhh[256 + col];
    float4 out;
    {
        float r = 1.f / (1.f + expf(-(rs.x + br.x + br2.x)));
        float z = 1.f / (1.f + expf(-(zs.x + bz.x + bz2.x)));
        float ng = tanhf(iv.x + bn.x + r * (hv.x + bn2.x));
        out.x = (1.f - z) * ng + z * h.x;
    }
    {
        float r = 1.f / (1.f + expf(-(rs.y + br.y + br2.y)));
        float z = 1.f / (1.f + expf(-(zs.y + bz.y + bz2.y)));
        float ng = tanhf(iv.y + bn.y + r * (hv.y + bn2.y));
        out.y = (1.f - z) * ng + z * h.y;
    }
    {
        float r = 1.f / (1.f + expf(-(rs.z + br.z + br2.z)));
        float z = 1.f / (1.f + expf(-(zs.z + bz.z + bz2.z)));
        float ng = tanhf(iv.z + bn.z + r * (hv.z + bn2.z));
        out.z = (1.f - z) * ng + z * h.z;
    }
    {
        float r = 1.f / (1.f + expf(-(rs.w + br.w + br2.w)));
        float z = 1.f / (1.f + expf(-(zs.w + bz.w + bz2.w)));
        float ng = tanhf(iv.w + bn.w + r * (hv.w + bn2.w));
        out.w = (1.f - z) * ng + z * h.w;
    }
    *(float4*)&g_h[o] = out;
}

// ---------------- pooling + classifier ----------------
__global__ void zero_feats_kernel() {
    int i = blockIdx.x * blockDim.x + threadIdx.x;
    if (i < BG * DD) g_feats[i] = 0.f;
}
__global__ void pool_kernel(const int* __restrict__ n2g) {
    int n0 = blockIdx.x * 64;
    int j  = threadIdx.x;
    if (n0 >= NN) return;
    float acc = 0.f;
    int cur = n2g[n0];
    for (int i = 0; i < 64; i++) {
        int n = n0 + i;
        if (n >= NN) break;
        int g = n2g[n];
        if (g != cur) {
            atomicAdd(&g_feats[cur * DD + j], acc);
            acc = 0.f; cur = g;
        }
        acc += g_h[n * DD + j] + g_h1[n * DD + j];
    }
    atomicAdd(&g_feats[cur * DD + j], acc);
}
__global__ void cls_kernel(const float* __restrict__ Wc,
                           const float* __restrict__ bc,
                           float* __restrict__ out) {
    int tid = threadIdx.x;
    if (tid >= BG * 2) return;
    int g = tid >> 1, c = tid & 1;
    float s = bc[c];
#pragma unroll 8
    for (int k = 0; k < DD; k++) s += g_feats[g * DD + k] * Wc[k * 2 + c];
    out[g * 2 + c] = s;
}

// ---------------- launch ----------------
#define GSMEM (4 * TILE_B)   // 139264

extern "C" void kernel_launch(void* const* d_in, const int* in_sizes, int n_in,
                              void* d_out, int out_size) {
    const float* features = (const float*)d_in[0];
    const int*   src      = (const int*)  d_in[1];
    const int*   dst      = (const int*)  d_in[2];
    const int*   etype    = (const int*)  d_in[3];
    const int*   n2g      = (const int*)  d_in[4];
    const float* W_msg    = (const float*)d_in[5];
    const float* b_msg    = (const float*)d_in[6];
    const float* w_ih     = (const float*)d_in[7];
    const float* b_ih     = (const float*)d_in[8];
    const float* w_hh     = (const float*)d_in[9];
    const float* b_hh     = (const float*)d_in[10];
    const float* W_cls    = (const float*)d_in[11];
    const float* b_cls    = (const float*)d_in[12];
    float* out = (float*)d_out;

    static int smem_set = 0;
    if (!smem_set) {
        cudaFuncSetAttribute(gemm3_kernel,
                             cudaFuncAttributeMaxDynamicSharedMemorySize, GSMEM);
        cudaFuncSetAttribute(gates_tc,
                             cudaFuncAttributeMaxDynamicSharedMemorySize, G6SMEM);
        smem_set = 1;
    }

    float *p_h, *p_t;
    __nv_bfloat16 *p_Wh, *p_Wl;
    cudaGetSymbolAddress((void**)&p_h,  g_h);
    cudaGetSymbolAddress((void**)&p_t,  g_t);
    cudaGetSymbolAddress((void**)&p_Wh, g_Wt_hi);
    cudaGetSymbolAddress((void**)&p_Wl, g_Wt_lo);

    // prologue: weights, init, CSR build
    prep_wmsg<<<(TT * DD * DD + 255) / 256, 256>>>(W_msg);
    prep_gates<<<(3 * DD * DD + 255) / 256, 256>>>(w_ih, w_hh);
    init_kernel<<<(NN * DD + 255) / 256, 256>>>(features);
    zero_cnt_kernel<<<(NN + 255) / 256, 256>>>();
    count_kernel<<<(EE + 255) / 256, 256>>>(dst);
    scan_a_kernel<<<NB1, 256>>>();
    scan_b_kernel<<<1, 256>>>();
    scan_c_kernel<<<(NN + 255) / 256, 256>>>();
    fill_kernel<<<(EE + 255) / 256, 256>>>(src, dst, etype);

    for (int s = 0; s < NSTEPS; s++) {
        gemm3_kernel<<<dim3(RTILES, TT), 256, GSMEM>>>(
            p_h, NN, p_Wh, p_Wl, b_msg, p_t, TT * DD);
        gather_kernel<<<(NN + 7) / 8, 256>>>();
        gates_tc<<<dim3(RTILES, 4), 256, G6SMEM>>>();
        gru_kernel<<<(NN * 32 + 255) / 256, 256>>>(b_ih, b_hh);
    }

    zero_feats_kernel<<<(BG * DD + 255) / 256, 256>>>();
    pool_kernel<<<(NN + 63) / 64, 128>>>(n2g);
    cls_kernel<<<1, 128>>>(W_cls, b_cls, out);
}